// round 2
// baseline (speedup 1.0000x reference)
#include <cuda_runtime.h>
#include <cstdint>

// DistMult forward scoring:
//   score[e] = sum_d h[src[e],d] * fwd_rel[etype[e],d] * h[dst[e],d]
// E = 640000, D = 128, h: [10000,128] f32, fwd_rel: [500,128] f32.
//
// NOTE: the reference builds src/dst/etype with jnp.int64, but JAX without
// x64 enabled silently produces int32 — the device buffers are int32.
//
// Strategy: warp-per-edge. Each of the three row gathers is a contiguous,
// 512B-aligned 512-byte read -> one float4 per lane, perfectly coalesced.
// h (5.1 MB) + fwd_rel (0.25 MB) live in L2, so the kernel is L2-BW bound
// (~983 MB of LTS reads total).

#define EMB_DIM 128

__global__ __launch_bounds__(256) void distmult_score_kernel(
    const float* __restrict__ h,
    const int* __restrict__ src,
    const int* __restrict__ dst,
    const int* __restrict__ etype,
    const float* __restrict__ fwd_rel,
    float* __restrict__ out,
    int n_edges)
{
    const int warp_id = (blockIdx.x * blockDim.x + threadIdx.x) >> 5;
    const int lane    = threadIdx.x & 31;
    if (warp_id >= n_edges) return;

    // Uniform per-warp index loads (LSU broadcasts same-address loads).
    const int s = src[warp_id];
    const int d = dst[warp_id];
    const int t = etype[warp_id];

    const float4* __restrict__ hu = reinterpret_cast<const float4*>(h + (size_t)s * EMB_DIM);
    const float4* __restrict__ hv = reinterpret_cast<const float4*>(h + (size_t)d * EMB_DIM);
    const float4* __restrict__ wr = reinterpret_cast<const float4*>(fwd_rel + (size_t)t * EMB_DIM);

    // Three independent 16B loads -> MLP=3 per lane, all L2 hits after warmup.
    const float4 a = hu[lane];
    const float4 b = wr[lane];
    const float4 c = hv[lane];

    float acc = a.x * b.x * c.x;
    acc = fmaf(a.y * b.y, c.y, acc);
    acc = fmaf(a.z * b.z, c.z, acc);
    acc = fmaf(a.w * b.w, c.w, acc);

    // Butterfly reduction across the warp.
    #pragma unroll
    for (int off = 16; off > 0; off >>= 1)
        acc += __shfl_xor_sync(0xffffffffu, acc, off);

    if (lane == 0) out[warp_id] = acc;
}

extern "C" void kernel_launch(void* const* d_in, const int* in_sizes, int n_in,
                              void* d_out, int out_size)
{
    const float* h       = (const float*)d_in[0];
    const int*   src     = (const int*)d_in[1];
    const int*   dst     = (const int*)d_in[2];
    const int*   etype   = (const int*)d_in[3];
    const float* fwd_rel = (const float*)d_in[4];
    // d_in[5] = rev_rel, unused in forward scoring.
    float* out = (float*)d_out;

    const int n_edges = in_sizes[1];           // src element count
    const int threads = 256;                   // 8 warps -> 8 edges per block
    const int blocks  = (n_edges + 7) / 8;

    distmult_score_kernel<<<blocks, threads>>>(h, src, dst, etype, fwd_rel,
                                               out, n_edges);
}

// round 3
// speedup vs baseline: 1.3720x; 1.3720x over previous
#include <cuda_runtime.h>
#include <cstdint>

// DistMult forward scoring:
//   score[e] = sum_d h[src[e],d] * fwd_rel[etype[e],d] * h[dst[e],d]
// E = 640000, D = 128. Index arrays are int32 on device (JAX x64 disabled).
//
// R3: 8 lanes per edge, 4 edges per warp.
//  - data wavefronts unchanged (irreducible volume: 1536B/edge through L1/L2)
//  - index/shuffle/store overhead amortized 4x across the warp
//  - 12 independent LDG.128 in flight per warp (MLP=12) hides L2 latency

#define EMB_DIM 128

__global__ __launch_bounds__(256) void distmult_score_kernel(
    const float* __restrict__ h,
    const int* __restrict__ src,
    const int* __restrict__ dst,
    const int* __restrict__ etype,
    const float* __restrict__ fwd_rel,
    float* __restrict__ out,
    int n_edges)
{
    const int warp_id = (blockIdx.x * blockDim.x + threadIdx.x) >> 5;
    const int lane    = threadIdx.x & 31;
    const int group   = lane >> 3;   // 0..3 : which edge within the warp
    const int sl      = lane & 7;    // 0..7 : sub-lane within the edge group

    const int e = warp_id * 4 + group;
    // n_edges = 640000 is divisible by 4; guard the whole warp uniformly so
    // partial warps at the tail stay convergent for the shuffles.
    if (e >= n_edges) return;

    // 4 distinct addresses per warp, 16B span -> 1 wavefront per array.
    const int s = src[e];
    const int d = dst[e];
    const int t = etype[e];

    const float4* __restrict__ hu = reinterpret_cast<const float4*>(h + (size_t)s * EMB_DIM);
    const float4* __restrict__ hv = reinterpret_cast<const float4*>(h + (size_t)d * EMB_DIM);
    const float4* __restrict__ wr = reinterpret_cast<const float4*>(fwd_rel + (size_t)t * EMB_DIM);

    // Each row = 32 float4. Sub-lane sl covers elements {sl, sl+8, sl+16, sl+24}:
    // per load instruction, each 8-lane group reads one contiguous 128B line.
    float4 a0, a1, a2, a3, b0, b1, b2, b3, c0, c1, c2, c3;
    a0 = hu[sl];      a1 = hu[sl + 8];  a2 = hu[sl + 16]; a3 = hu[sl + 24];
    b0 = wr[sl];      b1 = wr[sl + 8];  b2 = wr[sl + 16]; b3 = wr[sl + 24];
    c0 = hv[sl];      c1 = hv[sl + 8];  c2 = hv[sl + 16]; c3 = hv[sl + 24];

    float acc0 = a0.x * b0.x * c0.x;
    acc0 = fmaf(a0.y * b0.y, c0.y, acc0);
    acc0 = fmaf(a0.z * b0.z, c0.z, acc0);
    acc0 = fmaf(a0.w * b0.w, c0.w, acc0);

    float acc1 = a1.x * b1.x * c1.x;
    acc1 = fmaf(a1.y * b1.y, c1.y, acc1);
    acc1 = fmaf(a1.z * b1.z, c1.z, acc1);
    acc1 = fmaf(a1.w * b1.w, c1.w, acc1);

    float acc2 = a2.x * b2.x * c2.x;
    acc2 = fmaf(a2.y * b2.y, c2.y, acc2);
    acc2 = fmaf(a2.z * b2.z, c2.z, acc2);
    acc2 = fmaf(a2.w * b2.w, c2.w, acc2);

    float acc3 = a3.x * b3.x * c3.x;
    acc3 = fmaf(a3.y * b3.y, c3.y, acc3);
    acc3 = fmaf(a3.z * b3.z, c3.z, acc3);
    acc3 = fmaf(a3.w * b3.w, c3.w, acc3);

    float acc = (acc0 + acc1) + (acc2 + acc3);

    // Reduce across the 8 sub-lanes of each group (3 shuffles, all 4 edges at once).
    acc += __shfl_xor_sync(0xffffffffu, acc, 4);
    acc += __shfl_xor_sync(0xffffffffu, acc, 2);
    acc += __shfl_xor_sync(0xffffffffu, acc, 1);

    // Lanes 0,8,16,24 write out[e0..e3] -> contiguous 16B, 1 wavefront.
    if (sl == 0) out[e] = acc;
}

extern "C" void kernel_launch(void* const* d_in, const int* in_sizes, int n_in,
                              void* d_out, int out_size)
{
    const float* h       = (const float*)d_in[0];
    const int*   src     = (const int*)d_in[1];
    const int*   dst     = (const int*)d_in[2];
    const int*   etype   = (const int*)d_in[3];
    const float* fwd_rel = (const float*)d_in[4];
    // d_in[5] = rev_rel, unused in forward scoring.
    float* out = (float*)d_out;

    const int n_edges = in_sizes[1];               // src element count
    const int threads = 256;                       // 8 warps -> 32 edges per block
    const int edges_per_block = (threads / 32) * 4;
    const int blocks  = (n_edges + edges_per_block - 1) / edges_per_block;

    distmult_score_kernel<<<blocks, threads>>>(h, src, dst, etype, fwd_rel,
                                               out, n_edges);
}